// round 14
// baseline (speedup 1.0000x reference)
#include <cuda_runtime.h>
#include <math.h>
#include <stdint.h>

#define N_NODES 20000
#define E_EDGES 640000
#define GD 128
#define RR 8
#define KCAT (RR * GD)   // 1024

// ---------------- scratch (device globals) ----------------
__device__ float g_agg[(size_t)N_NODES * KCAT];
__device__ int   g_cnt[N_NODES * RR];
__device__ int   g_deg[N_NODES];
__device__ int   g_off[N_NODES + 1];
__device__ int   g_cur[N_NODES];
__device__ int   g_pk[E_EDGES];                   // packed src | (r<<16)
__device__ float g_h[N_NODES * GD];               // RGCN output
__device__ float g_w[N_NODES * GD];               // w = h@Wqk + cbias (dst-side attention vector)
__device__ float g_atg[N_NODES * GD];             // attention aggregate of h
__device__ float g_wqk[GD * GD];                  // (Wq @ Wk^T) / sqrt(d)
__device__ float g_cbias[GD];                     // (Wk @ bq) / sqrt(d)
__device__ float g_bvs[GD];                       // bv + bs

// ---------------- CSR build ----------------

__global__ void zero_ints() {
    int i = blockIdx.x * blockDim.x + threadIdx.x;
    int stride = gridDim.x * blockDim.x;
    for (int j = i; j < N_NODES * RR; j += stride) g_cnt[j] = 0;
    for (int j = i; j < N_NODES; j += stride) { g_deg[j] = 0; g_cur[j] = 0; }
}

__global__ void count_kernel(const int* __restrict__ ei, const int* __restrict__ et) {
    int i = blockIdx.x * blockDim.x + threadIdx.x;
    const int Q = E_EDGES / 4;
    if (i >= Q) return;
#pragma unroll
    for (int u = 0; u < 4; ++u) {
        int e = i + u * Q;
        int dst = ei[E_EDGES + e];
        int r = et[e];
        atomicAdd(&g_deg[dst], 1);
        atomicAdd(&g_cnt[dst * RR + r], 1);
    }
}

// single block, 1024 threads, per-thread chunk + 2-level warp scan
__global__ __launch_bounds__(1024) void scan_kernel() {
    __shared__ int warp_sums[32];
    int tid = threadIdx.x;
    const int CHUNK = (N_NODES + 1023) / 1024;   // 20
    int start = tid * CHUNK;
    int end = min(start + CHUNK, N_NODES);
    int sum = 0;
    for (int i = start; i < end; ++i) sum += g_deg[i];
    int lane = tid & 31, warp = tid >> 5;
    int v = sum;
#pragma unroll
    for (int o = 1; o < 32; o <<= 1) {
        int u = __shfl_up_sync(0xffffffffu, v, o);
        if (lane >= o) v += u;
    }
    if (lane == 31) warp_sums[warp] = v;
    __syncthreads();
    if (warp == 0) {
        int w = warp_sums[lane];
#pragma unroll
        for (int o = 1; o < 32; o <<= 1) {
            int u = __shfl_up_sync(0xffffffffu, w, o);
            if (lane >= o) w += u;
        }
        warp_sums[lane] = w;
    }
    __syncthreads();
    int excl = v - sum + (warp ? warp_sums[warp - 1] : 0);
    int run = excl;
    for (int i = start; i < end; ++i) { g_off[i] = run; run += g_deg[i]; }
    if (tid == 1023) g_off[N_NODES] = run;
}

__global__ void scatter_kernel(const int* __restrict__ ei, const int* __restrict__ et) {
    int i = blockIdx.x * blockDim.x + threadIdx.x;
    const int Q = E_EDGES / 4;
    if (i >= Q) return;
#pragma unroll
    for (int u = 0; u < 4; ++u) {
        int e = i + u * Q;
        int src = ei[e], dst = ei[E_EDGES + e], r = et[e];
        int pos = atomicAdd(&g_cur[dst], 1);
        g_pk[g_off[dst] + pos] = src | (r << 16);
    }
}

// ---------------- RGCN aggregation: block per dst ----------------
__global__ __launch_bounds__(128) void rgcn_agg(const float* __restrict__ x) {
    __shared__ float inv_s[RR];
    __shared__ int epk[128];
    int dst = blockIdx.x;
    int t = threadIdx.x;
    if (t < RR) {
        int c = g_cnt[dst * RR + t];
        inv_s[t] = 1.0f / (float)max(c, 1);
    }
    float acc[RR];
#pragma unroll
    for (int rr = 0; rr < RR; ++rr) acc[rr] = 0.f;
    int beg = g_off[dst], end = g_off[dst + 1];
    __syncthreads();
    for (int base = beg; base < end; base += 128) {
        int n = min(128, end - base);
        if (t < n) epk[t] = g_pk[base + t];
        __syncthreads();
#pragma unroll 4
        for (int j = 0; j < n; ++j) {
            int p = epk[j];
            int src = p & 0xFFFF;
            int r = p >> 16;
            float w = x[src * GD + t] * inv_s[r];
#pragma unroll
            for (int rr = 0; rr < RR; ++rr) acc[rr] += (rr == r) ? w : 0.f;
        }
        __syncthreads();
    }
    float* ap = &g_agg[(size_t)dst * KCAT + t];
#pragma unroll
    for (int rr = 0; rr < RR; ++rr) ap[rr * GD] = acc[rr];
}

// ---------------- attention precompute: Wqk = (Wq Wk^T)/sqrt(d), cbias, bvs ----------------
__global__ __launch_bounds__(128) void wqk_kernel(
    const float* __restrict__ Wq, const float* __restrict__ Wk,
    const float* __restrict__ bq, const float* __restrict__ bv,
    const float* __restrict__ bs)
{
    const float s = 0.08838834764831845f;   // 1/sqrt(128)
    int c = threadIdx.x;
    int e = blockIdx.x;
    if (e < GD) {
        __shared__ float qrow[GD];
        qrow[c] = Wq[e * GD + c];
        __syncthreads();
        const float4* wk4 = (const float4*)&Wk[c * GD];
        float acc = 0.f;
#pragma unroll
        for (int d4 = 0; d4 < GD / 4; ++d4) {
            float4 kv = wk4[d4];
            float4 qv = *(const float4*)&qrow[d4 * 4];
            acc += qv.x * kv.x + qv.y * kv.y + qv.z * kv.z + qv.w * kv.w;
        }
        g_wqk[e * GD + c] = acc * s;   // row e = contraction index, col c = output dim
    } else {
        float acc = 0.f;
        for (int d = 0; d < GD; ++d) acc += Wk[c * GD + d] * bq[d];
        g_cbias[c] = acc * s;
        g_bvs[c] = bv[c] + bs[c];
    }
}

// ---------------- tf32 tensor-core GEMM, double-buffered ----------------
__device__ __forceinline__ uint32_t f2tf32(float f) {
    uint32_t r;
    asm("cvt.rna.tf32.f32 %0, %1;" : "=r"(r) : "f"(f));
    return r;
}

__global__ __launch_bounds__(256) void gemm_tf32(
    const float* __restrict__ A, const float* __restrict__ B,
    const float* __restrict__ bias, float* __restrict__ C,
    const float* __restrict__ A2, const float* __restrict__ B2,
    int M, int K, int K2, int do_relu)
{
    __shared__ uint32_t As[2][128][20];
    __shared__ uint32_t Bs[2][16][136];

    int tid = threadIdx.x;
    int m0 = blockIdx.x * 128;
    int warp = tid >> 5, lane = tid & 31;
    int wm = warp >> 1, wn = warp & 1;
    int grp = lane >> 2, tig = lane & 3;

    float c[2][8][4];
#pragma unroll
    for (int mi = 0; mi < 2; ++mi)
#pragma unroll
        for (int ni = 0; ni < 8; ++ni)
#pragma unroll
            for (int j = 0; j < 4; ++j) c[mi][ni][j] = 0.f;

    int a_row = tid >> 1;
    int a_kc  = (tid & 1) << 3;
    int b_row0 = tid >> 5;
    int b_col = (tid & 31) << 2;

    int t1 = K >> 4;
    int t2 = (A2 != nullptr) ? (K2 >> 4) : 0;
    int T = t1 + t2;

    float ar[8], br[8];

    auto ldg_tile = [&](int t) {
        const float* Ap; const float* Bt; int Kp; int kk;
        if (t < t1) { Ap = A;  Bt = B;  Kp = K;  kk = t << 4; }
        else        { Ap = A2; Bt = B2; Kp = K2; kk = (t - t1) << 4; }
        float4 v0 = make_float4(0.f, 0.f, 0.f, 0.f), v1 = v0;
        int row = m0 + a_row;
        if (row < M) {
            const float* p = &Ap[(size_t)row * Kp + kk + a_kc];
            v0 = *(const float4*)p;
            v1 = *(const float4*)(p + 4);
        }
        ar[0] = v0.x; ar[1] = v0.y; ar[2] = v0.z; ar[3] = v0.w;
        ar[4] = v1.x; ar[5] = v1.y; ar[6] = v1.z; ar[7] = v1.w;
        const float* bp = &Bt[(size_t)(kk + b_row0) * GD + b_col];
        float4 w0 = *(const float4*)bp;
        float4 w1 = *(const float4*)(bp + 8 * GD);
        br[0] = w0.x; br[1] = w0.y; br[2] = w0.z; br[3] = w0.w;
        br[4] = w1.x; br[5] = w1.y; br[6] = w1.z; br[7] = w1.w;
    };
    auto st_tile = [&](int buf) {
#pragma unroll
        for (int i = 0; i < 8; ++i) As[buf][a_row][a_kc + i] = f2tf32(ar[i]);
#pragma unroll
        for (int i = 0; i < 4; ++i) {
            Bs[buf][b_row0][b_col + i]     = f2tf32(br[i]);
            Bs[buf][b_row0 + 8][b_col + i] = f2tf32(br[4 + i]);
        }
    };

    ldg_tile(0);
    st_tile(0);
    __syncthreads();

    for (int t = 0; t < T; ++t) {
        int buf = t & 1;
        if (t + 1 < T) ldg_tile(t + 1);

#pragma unroll
        for (int ks = 0; ks < 2; ++ks) {
            int kk = ks << 3;
            uint32_t a[2][4];
#pragma unroll
            for (int mi = 0; mi < 2; ++mi) {
                int r0 = wm * 32 + mi * 16 + grp;
                a[mi][0] = As[buf][r0][kk + tig];
                a[mi][1] = As[buf][r0 + 8][kk + tig];
                a[mi][2] = As[buf][r0][kk + tig + 4];
                a[mi][3] = As[buf][r0 + 8][kk + tig + 4];
            }
            uint32_t b[8][2];
#pragma unroll
            for (int ni = 0; ni < 8; ++ni) {
                int n = wn * 64 + ni * 8 + grp;
                b[ni][0] = Bs[buf][kk + tig][n];
                b[ni][1] = Bs[buf][kk + tig + 4][n];
            }
#pragma unroll
            for (int mi = 0; mi < 2; ++mi)
#pragma unroll
                for (int ni = 0; ni < 8; ++ni) {
                    asm volatile(
                        "mma.sync.aligned.m16n8k8.row.col.f32.tf32.tf32.f32 "
                        "{%0,%1,%2,%3}, {%4,%5,%6,%7}, {%8,%9}, {%0,%1,%2,%3};"
                        : "+f"(c[mi][ni][0]), "+f"(c[mi][ni][1]),
                          "+f"(c[mi][ni][2]), "+f"(c[mi][ni][3])
                        : "r"(a[mi][0]), "r"(a[mi][1]), "r"(a[mi][2]), "r"(a[mi][3]),
                          "r"(b[ni][0]), "r"(b[ni][1]));
                }
        }

        if (t + 1 < T) st_tile(buf ^ 1);
        __syncthreads();
    }

#pragma unroll
    for (int mi = 0; mi < 2; ++mi) {
        int rbase = m0 + wm * 32 + mi * 16 + grp;
#pragma unroll
        for (int ni = 0; ni < 8; ++ni) {
            int col = wn * 64 + ni * 8 + 2 * tig;
            float2 bv = *(const float2*)&bias[col];
            if (rbase < M) {
                float2 o;
                o.x = c[mi][ni][0] + bv.x;
                o.y = c[mi][ni][1] + bv.y;
                if (do_relu) { o.x = fmaxf(o.x, 0.f); o.y = fmaxf(o.y, 0.f); }
                *(float2*)&C[(size_t)rbase * GD + col] = o;
            }
            if (rbase + 8 < M) {
                float2 o;
                o.x = c[mi][ni][2] + bv.x;
                o.y = c[mi][ni][3] + bv.y;
                if (do_relu) { o.x = fmaxf(o.x, 0.f); o.y = fmaxf(o.y, 0.f); }
                *(float2*)&C[(size_t)(rbase + 8) * GD + col] = o;
            }
        }
    }
}

// ---------------- fused attention: score = w[dst].h[src], aggregate h ----------------
__global__ __launch_bounds__(128) void attn_kernel() {
    __shared__ float qs[GD];
    __shared__ int epk[128];
    __shared__ float wm[4], ws[4];
    __shared__ float wacc[4][GD];
    int dst = blockIdx.x;
    int t = threadIdx.x;
    int w = t >> 5, lane = t & 31;

    qs[t] = g_w[dst * GD + t];
    int beg = g_off[dst], end = g_off[dst + 1];
    __syncthreads();
    float4 qv = ((float4*)qs)[lane];

    const float4* h4 = (const float4*)g_h;

    float m = -INFINITY, s = 0.f;
    float4 acc = make_float4(0.f, 0.f, 0.f, 0.f);

    for (int base = beg; base < end; base += 128) {
        int n = min(128, end - base);
        if (t < n) epk[t] = g_pk[base + t];
        __syncthreads();
        for (int j = w; j < n; j += 8) {
            int j2 = j + 4;
            bool has2 = j2 < n;
            int src1 = epk[j] & 0xFFFF;
            int src2 = epk[has2 ? j2 : j] & 0xFFFF;
            float4 h1 = h4[src1 * 32 + lane];
            float4 h2 = h4[src2 * 32 + lane];
            float p1 = qv.x * h1.x + qv.y * h1.y + qv.z * h1.z + qv.w * h1.w;
            float p2 = qv.x * h2.x + qv.y * h2.y + qv.z * h2.z + qv.w * h2.w;
#pragma unroll
            for (int o = 16; o; o >>= 1) {
                p1 += __shfl_xor_sync(0xffffffffu, p1, o);
                p2 += __shfl_xor_sync(0xffffffffu, p2, o);
            }
            if (!has2) p2 = -INFINITY;

            float mn = fmaxf(m, fmaxf(p1, p2));
            float scale = __expf(m - mn);
            float e1 = __expf(p1 - mn);
            float e2 = has2 ? __expf(p2 - mn) : 0.f;
            s = s * scale + e1 + e2;
            acc.x = acc.x * scale + e1 * h1.x + e2 * h2.x;
            acc.y = acc.y * scale + e1 * h1.y + e2 * h2.y;
            acc.z = acc.z * scale + e1 * h1.z + e2 * h2.z;
            acc.w = acc.w * scale + e1 * h1.w + e2 * h2.w;
            m = mn;
        }
        __syncthreads();
    }

    if (lane == 0) { wm[w] = m; ws[w] = s; }
    ((float4*)wacc[w])[lane] = acc;
    __syncthreads();

    float M = fmaxf(fmaxf(wm[0], wm[1]), fmaxf(wm[2], wm[3]));
    float stot = 0.f, val = 0.f;
#pragma unroll
    for (int w2 = 0; w2 < 4; ++w2) {
        float sw = ws[w2];
        if (sw > 0.f) {
            float sc = __expf(wm[w2] - M);
            stot += sw * sc;
            val += wacc[w2][t] * sc;
        }
    }
    g_atg[dst * GD + t] = (stot > 0.f) ? (val / stot) : 0.f;
}

// ---------------- launch ----------------
extern "C" void kernel_launch(void* const* d_in, const int* in_sizes, int n_in,
                              void* d_out, int out_size) {
    const float* x     = (const float*)d_in[0];
    const int*   ei    = (const int*)d_in[1];
    const int*   et    = (const int*)d_in[2];
    const float* rw    = (const float*)d_in[3];
    const float* rroot = (const float*)d_in[4];
    const float* rbias = (const float*)d_in[5];
    const float* Wq    = (const float*)d_in[6];
    const float* bq    = (const float*)d_in[7];
    const float* Wk    = (const float*)d_in[8];
    const float* bk    = (const float*)d_in[9];
    const float* Wv    = (const float*)d_in[10];
    const float* bv    = (const float*)d_in[11];
    const float* Ws    = (const float*)d_in[12];
    const float* bs    = (const float*)d_in[13];
    float* out = (float*)d_out;
    (void)bk;   // cancels in softmax (per-dst constant)

    const int threads = 256;
    const int eqBlocks = (E_EDGES / 4 + threads - 1) / threads;
    const int mBlocks = (N_NODES + 127) / 128;

    float* d_h;   cudaGetSymbolAddress((void**)&d_h, g_h);
    float* d_w;   cudaGetSymbolAddress((void**)&d_w, g_w);
    float* d_atg; cudaGetSymbolAddress((void**)&d_atg, g_atg);
    float* d_agg; cudaGetSymbolAddress((void**)&d_agg, g_agg);
    float* d_wqk; cudaGetSymbolAddress((void**)&d_wqk, g_wqk);
    float* d_cb;  cudaGetSymbolAddress((void**)&d_cb, g_cbias);
    float* d_bvs; cudaGetSymbolAddress((void**)&d_bvs, g_bvs);

    // CSR build + attention weight precompute
    zero_ints<<<160, threads>>>();
    count_kernel<<<eqBlocks, threads>>>(ei, et);
    scan_kernel<<<1, 1024>>>();
    scatter_kernel<<<eqBlocks, threads>>>(ei, et);
    wqk_kernel<<<GD + 1, GD>>>(Wq, Wk, bq, bv, bs);

    // RGCN: aggregate, then fused GEMM h = relu(agg@Wcat + x@root + bias)
    rgcn_agg<<<N_NODES, 128>>>(x);
    gemm_tf32<<<mBlocks, threads>>>(d_agg, rw, rbias, d_h, x, rroot,
                                    N_NODES, KCAT, GD, 1);

    // w = h @ Wqk + cbias
    gemm_tf32<<<mBlocks, threads>>>(d_h, d_wqk, d_cb, d_w, nullptr, nullptr,
                                    N_NODES, GD, 0, 0);

    // attention aggregate of h (softmax over incoming edges)
    attn_kernel<<<N_NODES, 128>>>();

    // out = relu(atg@Wv + h@Ws + (bv+bs))
    gemm_tf32<<<mBlocks, threads>>>(d_atg, Wv, d_bvs, out, d_h, Ws,
                                    N_NODES, GD, GD, 1);
}

// round 15
// speedup vs baseline: 1.1246x; 1.1246x over previous
#include <cuda_runtime.h>
#include <math.h>
#include <stdint.h>

#define N_NODES 20000
#define E_EDGES 640000
#define GD 128
#define RR 8
#define KCAT (RR * GD)   // 1024

// ---------------- scratch (device globals) ----------------
__device__ float g_agg[(size_t)N_NODES * KCAT];
__device__ int   g_cnt[N_NODES * RR];
__device__ int   g_deg[N_NODES];
__device__ int   g_off[N_NODES + 1];
__device__ int   g_pos[E_EDGES];                  // per-edge slot within its dst segment
__device__ int   g_pk[E_EDGES];                   // packed src | (r<<16), CSR order
__device__ float g_h[N_NODES * GD];               // RGCN output
__device__ float g_w[N_NODES * GD];               // w = h@Wqk + cbias
__device__ float g_tmp[N_NODES * GD];             // tmp = h@Ws + (bv+bs)
__device__ float g_atg[N_NODES * GD];             // attention aggregate of h
__device__ float g_wqk[GD * GD];                  // (Wq @ Wk^T) / sqrt(d)
__device__ float g_cbias[GD];                     // (Wk @ bq) / sqrt(d)
__device__ float g_bvs[GD];                       // bv + bs
__device__ float g_zero[GD];                      // stays zero (bss), never written

// ---------------- CSR build ----------------

__global__ void zero_ints() {
    int i = blockIdx.x * blockDim.x + threadIdx.x;
    int stride = gridDim.x * blockDim.x;
    for (int j = i; j < N_NODES * RR; j += stride) g_cnt[j] = 0;
    for (int j = i; j < N_NODES; j += stride) g_deg[j] = 0;
}

// one atomic pass: records per-edge slot AND per-(dst,rel) counts
__global__ void count_pos_kernel(const int* __restrict__ ei, const int* __restrict__ et) {
    int i = blockIdx.x * blockDim.x + threadIdx.x;
    const int Q = E_EDGES / 4;
    if (i >= Q) return;
#pragma unroll
    for (int u = 0; u < 4; ++u) {
        int e = i + u * Q;
        int dst = ei[E_EDGES + e];
        int r = et[e];
        g_pos[e] = atomicAdd(&g_deg[dst], 1);
        atomicAdd(&g_cnt[dst * RR + r], 1);
    }
}

// single block, 1024 threads, per-thread chunk + 2-level warp scan
__global__ __launch_bounds__(1024) void scan_kernel() {
    __shared__ int warp_sums[32];
    int tid = threadIdx.x;
    const int CHUNK = (N_NODES + 1023) / 1024;   // 20
    int start = tid * CHUNK;
    int end = min(start + CHUNK, N_NODES);
    int sum = 0;
    for (int i = start; i < end; ++i) sum += g_deg[i];
    int lane = tid & 31, warp = tid >> 5;
    int v = sum;
#pragma unroll
    for (int o = 1; o < 32; o <<= 1) {
        int u = __shfl_up_sync(0xffffffffu, v, o);
        if (lane >= o) v += u;
    }
    if (lane == 31) warp_sums[warp] = v;
    __syncthreads();
    if (warp == 0) {
        int w = warp_sums[lane];
#pragma unroll
        for (int o = 1; o < 32; o <<= 1) {
            int u = __shfl_up_sync(0xffffffffu, w, o);
            if (lane >= o) w += u;
        }
        warp_sums[lane] = w;
    }
    __syncthreads();
    int excl = v - sum + (warp ? warp_sums[warp - 1] : 0);
    int run = excl;
    for (int i = start; i < end; ++i) { g_off[i] = run; run += g_deg[i]; }
    if (tid == 1023) g_off[N_NODES] = run;
}

// atomic-free scatter using recorded slots
__global__ void scatter_kernel(const int* __restrict__ ei, const int* __restrict__ et) {
    int i = blockIdx.x * blockDim.x + threadIdx.x;
    const int Q = E_EDGES / 4;
    if (i >= Q) return;
#pragma unroll
    for (int u = 0; u < 4; ++u) {
        int e = i + u * Q;
        int src = ei[e], dst = ei[E_EDGES + e], r = et[e];
        g_pk[g_off[dst] + g_pos[e]] = src | (r << 16);
    }
}

// ---------------- RGCN aggregation: block per dst, warp-per-edge float4 ----------------
__global__ __launch_bounds__(128) void rgcn_agg(const float* __restrict__ x) {
    __shared__ float inv_s[RR];
    __shared__ int epk[128];
    __shared__ float wred[4][RR][GD];   // 16KB cross-warp reduce buffer
    int dst = blockIdx.x;
    int t = threadIdx.x;
    int w = t >> 5, lane = t & 31;
    if (t < RR) {
        int c = g_cnt[dst * RR + t];
        inv_s[t] = 1.0f / (float)max(c, 1);
    }
    float4 acc[RR];
#pragma unroll
    for (int rr = 0; rr < RR; ++rr) acc[rr] = make_float4(0.f, 0.f, 0.f, 0.f);

    int beg = g_off[dst], end = g_off[dst + 1];
    const float4* x4 = (const float4*)x;
    __syncthreads();
    for (int base = beg; base < end; base += 128) {
        int n = min(128, end - base);
        if (t < n) epk[t] = g_pk[base + t];
        __syncthreads();
        for (int j = w; j < n; j += 8) {        // warp handles edges j, j+4, ... ILP-2
            int j2 = j + 4;
            bool has2 = j2 < n;
            int p1 = epk[j];
            int p2 = epk[has2 ? j2 : j];
            int src1 = p1 & 0xFFFF, r1 = p1 >> 16;
            int src2 = p2 & 0xFFFF, r2 = p2 >> 16;
            float4 v1 = x4[src1 * 32 + lane];
            float4 v2 = x4[src2 * 32 + lane];
#pragma unroll
            for (int rr = 0; rr < RR; ++rr) {
                float m1 = (rr == r1) ? 1.f : 0.f;
                float m2 = (has2 && rr == r2) ? 1.f : 0.f;
                acc[rr].x += m1 * v1.x + m2 * v2.x;
                acc[rr].y += m1 * v1.y + m2 * v2.y;
                acc[rr].z += m1 * v1.z + m2 * v2.z;
                acc[rr].w += m1 * v1.w + m2 * v2.w;
            }
        }
        __syncthreads();
    }

#pragma unroll
    for (int rr = 0; rr < RR; ++rr)
        ((float4*)&wred[w][rr][0])[lane] = acc[rr];
    __syncthreads();

    float* ap = &g_agg[(size_t)dst * KCAT];
#pragma unroll
    for (int rr = 0; rr < RR; ++rr) {
        float s = wred[0][rr][t] + wred[1][rr][t] + wred[2][rr][t] + wred[3][rr][t];
        ap[rr * GD + t] = s * inv_s[rr];
    }
}

// ---------------- attention precompute: Wqk = (Wq Wk^T)/sqrt(d), cbias, bvs ----------------
__global__ __launch_bounds__(128) void wqk_kernel(
    const float* __restrict__ Wq, const float* __restrict__ Wk,
    const float* __restrict__ bq, const float* __restrict__ bv,
    const float* __restrict__ bs)
{
    const float s = 0.08838834764831845f;   // 1/sqrt(128)
    int c = threadIdx.x;
    int e = blockIdx.x;
    if (e < GD) {
        __shared__ float qrow[GD];
        qrow[c] = Wq[e * GD + c];
        __syncthreads();
        const float4* wk4 = (const float4*)&Wk[c * GD];
        float acc = 0.f;
#pragma unroll
        for (int d4 = 0; d4 < GD / 4; ++d4) {
            float4 kv = wk4[d4];
            float4 qv = *(const float4*)&qrow[d4 * 4];
            acc += qv.x * kv.x + qv.y * kv.y + qv.z * kv.z + qv.w * kv.w;
        }
        g_wqk[e * GD + c] = acc * s;
    } else {
        float acc = 0.f;
        for (int d = 0; d < GD; ++d) acc += Wk[c * GD + d] * bq[d];
        g_cbias[c] = acc * s;
        g_bvs[c] = bv[c] + bs[c];
    }
}

// ---------------- tf32 tensor-core GEMM, double-buffered ----------------
// blockIdx.y in {0,1} selects (B, bias, C). Optional phase-2 (A2@B2) and
// optional element-wise addend Cadd (C = relu?(A@B + A2@B2 + bias + Cadd)).
__device__ __forceinline__ uint32_t f2tf32(float f) {
    uint32_t r;
    asm("cvt.rna.tf32.f32 %0, %1;" : "=r"(r) : "f"(f));
    return r;
}

__global__ __launch_bounds__(256) void gemm_tf32(
    const float* __restrict__ A,
    const float* __restrict__ B0, const float* __restrict__ B1,
    const float* __restrict__ b0, const float* __restrict__ b1,
    float* __restrict__ C0, float* __restrict__ C1,
    const float* __restrict__ A2, const float* __restrict__ B2,
    const float* __restrict__ Cadd,
    int M, int K, int K2, int do_relu)
{
    __shared__ uint32_t As[2][128][20];
    __shared__ uint32_t Bs[2][16][136];

    const float* B  = blockIdx.y ? B1 : B0;
    const float* bias = blockIdx.y ? b1 : b0;
    float* C = blockIdx.y ? C1 : C0;

    int tid = threadIdx.x;
    int m0 = blockIdx.x * 128;
    int warp = tid >> 5, lane = tid & 31;
    int wm = warp >> 1, wn = warp & 1;
    int grp = lane >> 2, tig = lane & 3;

    float c[2][8][4];
#pragma unroll
    for (int mi = 0; mi < 2; ++mi)
#pragma unroll
        for (int ni = 0; ni < 8; ++ni)
#pragma unroll
            for (int j = 0; j < 4; ++j) c[mi][ni][j] = 0.f;

    int a_row = tid >> 1;
    int a_kc  = (tid & 1) << 3;
    int b_row0 = tid >> 5;
    int b_col = (tid & 31) << 2;

    int t1 = K >> 4;
    int t2 = (A2 != nullptr) ? (K2 >> 4) : 0;
    int T = t1 + t2;

    float ar[8], br[8];

    auto ldg_tile = [&](int t) {
        const float* Ap; const float* Bt; int Kp; int kk;
        if (t < t1) { Ap = A;  Bt = B;  Kp = K;  kk = t << 4; }
        else        { Ap = A2; Bt = B2; Kp = K2; kk = (t - t1) << 4; }
        float4 v0 = make_float4(0.f, 0.f, 0.f, 0.f), v1 = v0;
        int row = m0 + a_row;
        if (row < M) {
            const float* p = &Ap[(size_t)row * Kp + kk + a_kc];
            v0 = *(const float4*)p;
            v1 = *(const float4*)(p + 4);
        }
        ar[0] = v0.x; ar[1] = v0.y; ar[2] = v0.z; ar[3] = v0.w;
        ar[4] = v1.x; ar[5] = v1.y; ar[6] = v1.z; ar[7] = v1.w;
        const float* bp = &Bt[(size_t)(kk + b_row0) * GD + b_col];
        float4 w0 = *(const float4*)bp;
        float4 w1 = *(const float4*)(bp + 8 * GD);
        br[0] = w0.x; br[1] = w0.y; br[2] = w0.z; br[3] = w0.w;
        br[4] = w1.x; br[5] = w1.y; br[6] = w1.z; br[7] = w1.w;
    };
    auto st_tile = [&](int buf) {
#pragma unroll
        for (int i = 0; i < 8; ++i) As[buf][a_row][a_kc + i] = f2tf32(ar[i]);
#pragma unroll
        for (int i = 0; i < 4; ++i) {
            Bs[buf][b_row0][b_col + i]     = f2tf32(br[i]);
            Bs[buf][b_row0 + 8][b_col + i] = f2tf32(br[4 + i]);
        }
    };

    ldg_tile(0);
    st_tile(0);
    __syncthreads();

    for (int t = 0; t < T; ++t) {
        int buf = t & 1;
        if (t + 1 < T) ldg_tile(t + 1);

#pragma unroll
        for (int ks = 0; ks < 2; ++ks) {
            int kk = ks << 3;
            uint32_t a[2][4];
#pragma unroll
            for (int mi = 0; mi < 2; ++mi) {
                int r0 = wm * 32 + mi * 16 + grp;
                a[mi][0] = As[buf][r0][kk + tig];
                a[mi][1] = As[buf][r0 + 8][kk + tig];
                a[mi][2] = As[buf][r0][kk + tig + 4];
                a[mi][3] = As[buf][r0 + 8][kk + tig + 4];
            }
            uint32_t b[8][2];
#pragma unroll
            for (int ni = 0; ni < 8; ++ni) {
                int n = wn * 64 + ni * 8 + grp;
                b[ni][0] = Bs[buf][kk + tig][n];
                b[ni][1] = Bs[buf][kk + tig + 4][n];
            }
#pragma unroll
            for (int mi = 0; mi < 2; ++mi)
#pragma unroll
                for (int ni = 0; ni < 8; ++ni) {
                    asm volatile(
                        "mma.sync.aligned.m16n8k8.row.col.f32.tf32.tf32.f32 "
                        "{%0,%1,%2,%3}, {%4,%5,%6,%7}, {%8,%9}, {%0,%1,%2,%3};"
                        : "+f"(c[mi][ni][0]), "+f"(c[mi][ni][1]),
                          "+f"(c[mi][ni][2]), "+f"(c[mi][ni][3])
                        : "r"(a[mi][0]), "r"(a[mi][1]), "r"(a[mi][2]), "r"(a[mi][3]),
                          "r"(b[ni][0]), "r"(b[ni][1]));
                }
        }

        if (t + 1 < T) st_tile(buf ^ 1);
        __syncthreads();
    }

#pragma unroll
    for (int mi = 0; mi < 2; ++mi) {
        int rbase = m0 + wm * 32 + mi * 16 + grp;
#pragma unroll
        for (int ni = 0; ni < 8; ++ni) {
            int col = wn * 64 + ni * 8 + 2 * tig;
            float2 bv = *(const float2*)&bias[col];
            if (rbase < M) {
                float2 o;
                o.x = c[mi][ni][0] + bv.x;
                o.y = c[mi][ni][1] + bv.y;
                if (Cadd) {
                    float2 ca = *(const float2*)&Cadd[(size_t)rbase * GD + col];
                    o.x += ca.x; o.y += ca.y;
                }
                if (do_relu) { o.x = fmaxf(o.x, 0.f); o.y = fmaxf(o.y, 0.f); }
                *(float2*)&C[(size_t)rbase * GD + col] = o;
            }
            if (rbase + 8 < M) {
                float2 o;
                o.x = c[mi][ni][2] + bv.x;
                o.y = c[mi][ni][3] + bv.y;
                if (Cadd) {
                    float2 ca = *(const float2*)&Cadd[(size_t)(rbase + 8) * GD + col];
                    o.x += ca.x; o.y += ca.y;
                }
                if (do_relu) { o.x = fmaxf(o.x, 0.f); o.y = fmaxf(o.y, 0.f); }
                *(float2*)&C[(size_t)(rbase + 8) * GD + col] = o;
            }
        }
    }
}

// ---------------- fused attention: score = w[dst].h[src], aggregate h ----------------
__global__ __launch_bounds__(128) void attn_kernel() {
    __shared__ int epk[128];
    __shared__ float wm[4], ws[4];
    __shared__ float wacc[4][GD];
    int dst = blockIdx.x;
    int t = threadIdx.x;
    int w = t >> 5, lane = t & 31;

    float4 qv = ((const float4*)g_w)[dst * 32 + lane];
    int beg = g_off[dst], end = g_off[dst + 1];

    const float4* h4 = (const float4*)g_h;

    float m = -INFINITY, s = 0.f;
    float4 acc = make_float4(0.f, 0.f, 0.f, 0.f);

    for (int base = beg; base < end; base += 128) {
        int n = min(128, end - base);
        if (t < n) epk[t] = g_pk[base + t];
        __syncthreads();
        for (int j = w; j < n; j += 8) {
            int j2 = j + 4;
            bool has2 = j2 < n;
            int src1 = epk[j] & 0xFFFF;
            int src2 = epk[has2 ? j2 : j] & 0xFFFF;
            float4 h1 = h4[src1 * 32 + lane];
            float4 h2 = h4[src2 * 32 + lane];
            float p1 = qv.x * h1.x + qv.y * h1.y + qv.z * h1.z + qv.w * h1.w;
            float p2 = qv.x * h2.x + qv.y * h2.y + qv.z * h2.z + qv.w * h2.w;
#pragma unroll
            for (int o = 16; o; o >>= 1) {
                p1 += __shfl_xor_sync(0xffffffffu, p1, o);
                p2 += __shfl_xor_sync(0xffffffffu, p2, o);
            }
            if (!has2) p2 = -INFINITY;

            float mn = fmaxf(m, fmaxf(p1, p2));
            float scale = __expf(m - mn);
            float e1 = __expf(p1 - mn);
            float e2 = has2 ? __expf(p2 - mn) : 0.f;
            s = s * scale + e1 + e2;
            acc.x = acc.x * scale + e1 * h1.x + e2 * h2.x;
            acc.y = acc.y * scale + e1 * h1.y + e2 * h2.y;
            acc.z = acc.z * scale + e1 * h1.z + e2 * h2.z;
            acc.w = acc.w * scale + e1 * h1.w + e2 * h2.w;
            m = mn;
        }
        __syncthreads();
    }

    if (lane == 0) { wm[w] = m; ws[w] = s; }
    ((float4*)wacc[w])[lane] = acc;
    __syncthreads();

    float M = fmaxf(fmaxf(wm[0], wm[1]), fmaxf(wm[2], wm[3]));
    float stot = 0.f, val = 0.f;
#pragma unroll
    for (int w2 = 0; w2 < 4; ++w2) {
        float sw = ws[w2];
        if (sw > 0.f) {
            float sc = __expf(wm[w2] - M);
            stot += sw * sc;
            val += wacc[w2][t] * sc;
        }
    }
    g_atg[dst * GD + t] = (stot > 0.f) ? (val / stot) : 0.f;
}

// ---------------- launch ----------------
extern "C" void kernel_launch(void* const* d_in, const int* in_sizes, int n_in,
                              void* d_out, int out_size) {
    const float* x     = (const float*)d_in[0];
    const int*   ei    = (const int*)d_in[1];
    const int*   et    = (const int*)d_in[2];
    const float* rw    = (const float*)d_in[3];
    const float* rroot = (const float*)d_in[4];
    const float* rbias = (const float*)d_in[5];
    const float* Wq    = (const float*)d_in[6];
    const float* bq    = (const float*)d_in[7];
    const float* Wk    = (const float*)d_in[8];
    const float* bk    = (const float*)d_in[9];
    const float* Wv    = (const float*)d_in[10];
    const float* bv    = (const float*)d_in[11];
    const float* Ws    = (const float*)d_in[12];
    const float* bs    = (const float*)d_in[13];
    float* out = (float*)d_out;
    (void)bk;   // cancels in softmax (per-dst constant)

    const int threads = 256;
    const int eqBlocks = (E_EDGES / 4 + threads - 1) / threads;
    const int mBlocks = (N_NODES + 127) / 128;

    float* d_h;   cudaGetSymbolAddress((void**)&d_h, g_h);
    float* d_w;   cudaGetSymbolAddress((void**)&d_w, g_w);
    float* d_tmp; cudaGetSymbolAddress((void**)&d_tmp, g_tmp);
    float* d_atg; cudaGetSymbolAddress((void**)&d_atg, g_atg);
    float* d_agg; cudaGetSymbolAddress((void**)&d_agg, g_agg);
    float* d_wqk; cudaGetSymbolAddress((void**)&d_wqk, g_wqk);
    float* d_cb;  cudaGetSymbolAddress((void**)&d_cb, g_cbias);
    float* d_bvs; cudaGetSymbolAddress((void**)&d_bvs, g_bvs);
    float* d_z;   cudaGetSymbolAddress((void**)&d_z, g_zero);

    // CSR build + attention weight precompute
    zero_ints<<<160, threads>>>();
    count_pos_kernel<<<eqBlocks, threads>>>(ei, et);
    scan_kernel<<<1, 1024>>>();
    scatter_kernel<<<eqBlocks, threads>>>(ei, et);
    wqk_kernel<<<GD + 1, GD>>>(Wq, Wk, bq, bv, bs);

    // RGCN: aggregate, then h = relu(agg@Wcat + x@root + bias)
    rgcn_agg<<<N_NODES, 128>>>(x);
    gemm_tf32<<<dim3(mBlocks, 1), threads>>>(
        d_agg, rw, nullptr, rbias, nullptr, d_h, nullptr,
        x, rroot, nullptr, N_NODES, KCAT, GD, 1);

    // one launch, two outputs sharing A=h:  w = h@Wqk + cb ;  tmp = h@Ws + (bv+bs)
    gemm_tf32<<<dim3(mBlocks, 2), threads>>>(
        d_h, d_wqk, Ws, d_cb, d_bvs, d_w, d_tmp,
        nullptr, nullptr, nullptr, N_NODES, GD, 0, 0);

    // attention aggregate of h (softmax over incoming edges)
    attn_kernel<<<N_NODES, 128>>>();

    // out = relu(atg@Wv + tmp)
    gemm_tf32<<<dim3(mBlocks, 1), threads>>>(
        d_atg, Wv, nullptr, d_z, nullptr, out, nullptr,
        nullptr, nullptr, d_tmp, N_NODES, GD, 0, 1);
}